// round 13
// baseline (speedup 1.0000x reference)
#include <cuda_runtime.h>

#define HH 128
#define WW 128
#define HWSZ 16384
#define CIN 64
#define CMID 16
#define NMAX 4

#define TX 16
#define TY 16
#define RAD 4
#define HX 24
#define HY 24        // halo rows: 16 + 2*4
#define FSTR 20      // floats per halo pixel (16 f2 + norm + ou.x + ou.y + pad)
#define S_ROW (HX * FSTR)   // 480 floats per halo row

// Scratch (device globals — no allocation allowed)
__device__ float g_f1[NMAX * HWSZ * CMID];   // [N, HW, 16]
__device__ float g_f2[NMAX * HWSZ * CMID];   // [N, HW, 16]
__device__ float g_oup[NMAX * HWSZ * 2];     // [N, HW, 2]

typedef unsigned long long u64;

__device__ __forceinline__ u64 pack2(float a, float b) {
    u64 r; asm("mov.b64 %0, {%1,%2};" : "=l"(r) : "f"(a), "f"(b)); return r;
}
__device__ __forceinline__ float2 unpack2(u64 v) {
    float2 r; asm("mov.b64 {%0,%1}, %2;" : "=f"(r.x), "=f"(r.y) : "l"(v)); return r;
}
__device__ __forceinline__ u64 fma2(u64 a, u64 b, u64 c) {
    u64 d; asm("fma.rn.f32x2 %0, %1, %2, %3;" : "=l"(d) : "l"(a), "l"(b), "l"(c)); return d;
}
__device__ __forceinline__ u64 add2(u64 a, u64 b) {
    u64 d; asm("add.rn.f32x2 %0, %1, %2;" : "=l"(d) : "l"(a), "l"(b)); return d;
}

__device__ __forceinline__ int refl(int i, int n) {
    if (i < 0) i = -i;
    if (i >= n) i = 2 * n - 2 - i;
    return i;
}

// Kernel 1 (unchanged from R8/R10, measured ~6us): BOTH 1x1 convs in one pass
// over delta; broadcast LDS.128 weights; delta loads double-buffered 8-wide.
// Plus bilinear upsample of out.
__global__ __launch_bounds__(128) void prep_kernel(
    const float* __restrict__ delta,
    const float* __restrict__ outc,
    const float* __restrict__ w1, const float* __restrict__ b1,
    const float* __restrict__ w2, const float* __restrict__ b2,
    int N) {
    __shared__ __align__(16) float s_w1[CMID * CIN];
    __shared__ __align__(16) float s_w2[CMID * CIN];
    for (int i = threadIdx.x; i < CMID * CIN; i += 128) {
        s_w1[i] = w1[i];
        s_w2[i] = w2[i];
    }
    __syncthreads();

    int p = blockIdx.x * 128 + threadIdx.x;
    if (p >= N * HWSZ) return;
    int n = p >> 14;
    int yx = p & (HWSZ - 1);

    u64 acc1[CMID], acc2[CMID];
#pragma unroll
    for (int o = 0; o < CMID; o++) { acc1[o] = 0ULL; acc2[o] = 0ULL; }

    const float* dptr = delta + (size_t)n * CIN * HWSZ + yx;
    float d[8], dn[8];
#pragma unroll
    for (int k = 0; k < 8; k++) d[k] = __ldg(dptr + k * HWSZ);

#pragma unroll 1
    for (int c0 = 0; c0 < CIN; c0 += 8) {
        int cn = (c0 + 8 < CIN) ? (c0 + 8) : 0;
#pragma unroll
        for (int k = 0; k < 8; k++) dn[k] = __ldg(dptr + (cn + k) * HWSZ);
#pragma unroll
        for (int kk = 0; kk < 8; kk += 4) {
            u64 dA = pack2(d[kk + 0], d[kk + 1]);
            u64 dB = pack2(d[kk + 2], d[kk + 3]);
#pragma unroll
            for (int o = 0; o < CMID; o++) {
                ulonglong2 wa = *(const ulonglong2*)(s_w1 + o * CIN + c0 + kk);
                ulonglong2 wb = *(const ulonglong2*)(s_w2 + o * CIN + c0 + kk);
                acc1[o] = fma2(dA, wa.x, acc1[o]);
                acc1[o] = fma2(dB, wa.y, acc1[o]);
                acc2[o] = fma2(dA, wb.x, acc2[o]);
                acc2[o] = fma2(dB, wb.y, acc2[o]);
            }
        }
#pragma unroll
        for (int k = 0; k < 8; k++) d[k] = dn[k];
    }

    float4* f1o = (float4*)(g_f1 + (size_t)p * CMID);
    float4* f2o = (float4*)(g_f2 + (size_t)p * CMID);
#pragma unroll
    for (int j = 0; j < 4; j++) {
        float2 e0 = unpack2(acc1[4 * j + 0]);
        float2 e1 = unpack2(acc1[4 * j + 1]);
        float2 e2 = unpack2(acc1[4 * j + 2]);
        float2 e3 = unpack2(acc1[4 * j + 3]);
        f1o[j] = make_float4(b1[4 * j + 0] + e0.x + e0.y,
                             b1[4 * j + 1] + e1.x + e1.y,
                             b1[4 * j + 2] + e2.x + e2.y,
                             b1[4 * j + 3] + e3.x + e3.y);
        float2 g0 = unpack2(acc2[4 * j + 0]);
        float2 g1 = unpack2(acc2[4 * j + 1]);
        float2 g2 = unpack2(acc2[4 * j + 2]);
        float2 g3 = unpack2(acc2[4 * j + 3]);
        f2o[j] = make_float4(b2[4 * j + 0] + g0.x + g0.y,
                             b2[4 * j + 1] + g1.x + g1.y,
                             b2[4 * j + 2] + g2.x + g2.y,
                             b2[4 * j + 3] + g3.x + g3.y);
    }

    // Bilinear upsample (align_corners=True) of out [N,2,64,64]
    int y = yx >> 7, x = yx & 127;
    const float scl = 63.0f / 127.0f;
    float sy = y * scl, sx = x * scl;
    int y0i = (int)sy, x0i = (int)sx;
    if (y0i > 62) y0i = 62;
    if (x0i > 62) x0i = 62;
    float wy = sy - y0i, wx = sx - x0i;
    const float* ob = outc + (size_t)n * 2 * 4096;
#pragma unroll
    for (int c = 0; c < 2; c++) {
        const float* oc = ob + c * 4096;
        float v00 = oc[y0i * 64 + x0i];
        float v01 = oc[y0i * 64 + x0i + 1];
        float v10 = oc[(y0i + 1) * 64 + x0i];
        float v11 = oc[(y0i + 1) * 64 + x0i + 1];
        float top = v00 * (1.0f - wx) + v01 * wx;
        float bot = v10 * (1.0f - wx) + v11 * wx;
        g_oup[(size_t)p * 2 + c] = top * (1.0f - wy) + bot * wy;
    }
}

// Kernel 2: 16x16 tile, 256 threads. Thread PAIR (even/odd lane) owns a
// vertical pixel pair; each halo read serves a tap of A and of B. h=tid&1
// splits dx interleaved -> conflict-free. ab loads software-pipelined one
// row ahead (reg headroom exists: grid-limited occupancy). Edge-row and
// dx-clamp ab loads predicated off.
__global__ __launch_bounds__(256) void main_kernel(
    const float* __restrict__ ab,
    const float* __restrict__ gdp,
    const float* __restrict__ gsp,
    float* __restrict__ outr) {
    __shared__ __align__(16) float s_f2[HY * S_ROW];   // 46080 B

    const int tid = threadIdx.x;
    const int x0 = blockIdx.x * TX, y0 = blockIdx.y * TY;
    const int n = blockIdx.z;
    const float gd = *gdp;
    const float gs = *gsp;

    // Halo load with reflect mapping + norm precompute (24x24 pixels)
    for (int i = tid; i < HY * HX; i += 256) {
        int hy = i / HX, hx = i - hy * HX;
        int gy = refl(y0 - RAD + hy, HH);
        int gx = refl(x0 - RAD + hx, WW);
        int gp = (n << 14) + (gy << 7) + gx;
        const float4* src = (const float4*)(g_f2 + (size_t)gp * CMID);
        float4 a0 = src[0], a1 = src[1], a2 = src[2], a3 = src[3];
        float nf2 = 0.f;
        nf2 = fmaf(a0.x, a0.x, fmaf(a0.y, a0.y, fmaf(a0.z, a0.z, fmaf(a0.w, a0.w, nf2))));
        nf2 = fmaf(a1.x, a1.x, fmaf(a1.y, a1.y, fmaf(a1.z, a1.z, fmaf(a1.w, a1.w, nf2))));
        nf2 = fmaf(a2.x, a2.x, fmaf(a2.y, a2.y, fmaf(a2.z, a2.z, fmaf(a2.w, a2.w, nf2))));
        nf2 = fmaf(a3.x, a3.x, fmaf(a3.y, a3.y, fmaf(a3.z, a3.z, fmaf(a3.w, a3.w, nf2))));
        float4* dst = (float4*)(s_f2 + hy * S_ROW + hx * FSTR);
        dst[0] = a0; dst[1] = a1; dst[2] = a2; dst[3] = a3;
        float2 ov = *(const float2*)(g_oup + (size_t)gp * 2);
        dst[4] = make_float4(-gd * nf2, ov.x, ov.y, 0.f);
    }
    __syncthreads();

    const int pair = tid >> 1;        // 0..127
    const int h = tid & 1;            // dx-interleave half
    const int px = pair & 15, py2 = pair >> 4;   // px 0..15, py2 0..7
    const int yxA = ((y0 + 2 * py2) << 7) + (x0 + px);
    const int yxB = yxA + 128;
    const int pA = (n << 14) + yxA;

    // f1 for both pixels, scaled by 2*gd; c1 = -gd*|f1|^2
    u64 f1A[8], f1B[8];
    float c1A, c1B;
    {
        const float tg = 2.f * gd;
        const float4* fpA = (const float4*)(g_f1 + (size_t)pA * CMID);
        const float4* fpB = (const float4*)(g_f1 + (size_t)(pA + 128) * CMID);
        float nfa = 0.f, nfb = 0.f;
#pragma unroll
        for (int j = 0; j < 4; j++) {
            float4 v = fpA[j];
            nfa = fmaf(v.x, v.x, fmaf(v.y, v.y, fmaf(v.z, v.z, fmaf(v.w, v.w, nfa))));
            f1A[2 * j + 0] = pack2(tg * v.x, tg * v.y);
            f1A[2 * j + 1] = pack2(tg * v.z, tg * v.w);
            float4 u = fpB[j];
            nfb = fmaf(u.x, u.x, fmaf(u.y, u.y, fmaf(u.z, u.z, fmaf(u.w, u.w, nfb))));
            f1B[2 * j + 0] = pack2(tg * u.x, tg * u.y);
            f1B[2 * j + 1] = pack2(tg * u.z, tg * u.w);
        }
        c1A = -gd * nfa;
        c1B = -gd * nfb;
    }

    const float* abbase = ab + (size_t)n * 81 * HWSZ;
    float sA = 0.f, aA0 = 0.f, aA1 = 0.f;
    float sB = 0.f, aB0 = 0.f, aB1 = 0.f;

    // ab values for the current row: A uses window-row rr, B uses rr-1.
    float avA[5], avB[5];
    {
        const float* abA = abbase + yxA;   // row 0 for pixel A
#pragma unroll
        for (int i = 0; i < 5; i++) {
            int dx = 2 * i + h;
            avA[i] = (dx <= 8) ? __ldg(abA + (size_t)dx * HWSZ) : 0.f;
            avB[i] = 0.f;
        }
    }

#pragma unroll 1
    for (int rr = 0; rr < 10; rr++) {
        const int hr = 2 * py2 + rr;                // halo row (0..23)
        const float* rowsh = s_f2 + hr * S_ROW + px * FSTR;
        const bool vA = (rr < 9);                   // uniform
        const bool vB = (rr > 0);

        // prefetch next iteration's ab rows (uniform guards; predicated-off
        // loads for dx>8 never issue)
        float nvA[5], nvB[5];
        if (rr < 8) {
            const float* abAn = abbase + (size_t)((rr + 1) * 9) * HWSZ + yxA;
#pragma unroll
            for (int i = 0; i < 5; i++) {
                int dx = 2 * i + h;
                nvA[i] = (dx <= 8) ? __ldg(abAn + (size_t)dx * HWSZ) : 0.f;
            }
        }
        if (rr < 9) {
            const float* abBn = abbase + (size_t)(rr * 9) * HWSZ + yxB;
#pragma unroll
            for (int i = 0; i < 5; i++) {
                int dx = 2 * i + h;
                nvB[i] = (dx <= 8) ? __ldg(abBn + (size_t)dx * HWSZ) : 0.f;
            }
        }

#pragma unroll
        for (int i = 0; i < 5; i++) {
            const int dx = 2 * i + h;
            if (dx <= 8) {                          // off only for h=1,i=4
                const ulonglong2* fp = (const ulonglong2*)(rowsh + dx * FSTR);
                ulonglong2 q0 = fp[0], q1 = fp[1];
                ulonglong2 q2 = fp[2], q3 = fp[3];
                float4 oc = *(const float4*)(rowsh + dx * FSTR + 16);
                if (vA) {
                    u64 A = fma2(f1A[0], q0.x, 0ULL);
                    u64 B = fma2(f1A[1], q0.y, 0ULL);
                    A = fma2(f1A[2], q1.x, A);
                    B = fma2(f1A[3], q1.y, B);
                    A = fma2(f1A[4], q2.x, A);
                    B = fma2(f1A[5], q2.y, B);
                    A = fma2(f1A[6], q3.x, A);
                    B = fma2(f1A[7], q3.y, B);
                    float2 dp = unpack2(add2(A, B));
                    float logit = fmaf(gs, avA[i], c1A + oc.x + dp.x + dp.y);
                    float w = __expf(logit);
                    sA += w;
                    aA0 = fmaf(w, oc.y, aA0);
                    aA1 = fmaf(w, oc.z, aA1);
                }
                if (vB) {
                    u64 A = fma2(f1B[0], q0.x, 0ULL);
                    u64 B = fma2(f1B[1], q0.y, 0ULL);
                    A = fma2(f1B[2], q1.x, A);
                    B = fma2(f1B[3], q1.y, B);
                    A = fma2(f1B[4], q2.x, A);
                    B = fma2(f1B[5], q2.y, B);
                    A = fma2(f1B[6], q3.x, A);
                    B = fma2(f1B[7], q3.y, B);
                    float2 dp = unpack2(add2(A, B));
                    float logit = fmaf(gs, avB[i], c1B + oc.x + dp.x + dp.y);
                    float w = __expf(logit);
                    sB += w;
                    aB0 = fmaf(w, oc.y, aB0);
                    aB1 = fmaf(w, oc.z, aB1);
                }
            }
        }

#pragma unroll
        for (int i = 0; i < 5; i++) { avA[i] = nvA[i]; avB[i] = nvB[i]; }
    }

    // combine dx halves (lanes 2i <-> 2i+1)
    sA  += __shfl_xor_sync(0xFFFFFFFFu, sA, 1);
    aA0 += __shfl_xor_sync(0xFFFFFFFFu, aA0, 1);
    aA1 += __shfl_xor_sync(0xFFFFFFFFu, aA1, 1);
    sB  += __shfl_xor_sync(0xFFFFFFFFu, sB, 1);
    aB0 += __shfl_xor_sync(0xFFFFFFFFu, aB0, 1);
    aB1 += __shfl_xor_sync(0xFFFFFFFFu, aB1, 1);

    if (h == 0) {
        float inv = 1.f / sA;
        outr[((size_t)(n * 2) << 14) + yxA] = aA0 * inv;
        outr[((size_t)(n * 2 + 1) << 14) + yxA] = aA1 * inv;
    } else {
        float inv = 1.f / sB;
        outr[((size_t)(n * 2) << 14) + yxB] = aB0 * inv;
        outr[((size_t)(n * 2 + 1) << 14) + yxB] = aB1 * inv;
    }
}

extern "C" void kernel_launch(void* const* d_in, const int* in_sizes, int n_in,
                              void* d_out, int out_size) {
    const float* delta = (const float*)d_in[0];
    const float* outc  = (const float*)d_in[1];
    const float* ab    = (const float*)d_in[2];
    const float* w1    = (const float*)d_in[3];
    const float* b1    = (const float*)d_in[4];
    const float* w2    = (const float*)d_in[5];
    const float* b2    = (const float*)d_in[6];
    const float* gd    = (const float*)d_in[7];
    const float* gs    = (const float*)d_in[8];

    int N = in_sizes[0] / (CIN * HWSZ);
    if (N > NMAX) N = NMAX;

    prep_kernel<<<(N * HWSZ + 127) / 128, 128>>>(delta, outc, w1, b1, w2, b2, N);
    main_kernel<<<dim3(WW / TX, HH / TY, N), dim3(256)>>>(ab, gd, gs, (float*)d_out);
}